// round 7
// baseline (speedup 1.0000x reference)
#include <cuda_runtime.h>
#include <math.h>

#define G  4384
#define D  128
#define B  8
#define H1 64
#define NOUT 26
#define QB 8                  // queries per chunk (G/QB = 548 exact)
#define NT 512                // threads per block in fused kernel
#define NCHUNK (G / QB)       // 548
#define NTASK  (NCHUNK * B)   // 4384
#define NSM 148

// ---------------- device scratch ----------------
__device__ float4 g_P4[G];              // P'[k] = (W_in @ K^T)*scale*log2e
__device__ float  g_c[G];               // c'[k]
__device__ float  g_acc[B * G + B * D]; // only [B*G, B*G+B*D) used now (mean partials)
__device__ float  g_wpart[(size_t)B * NCHUNK * G];  // per-(b,chunk) partial column sums (76.8 MB)

__device__ __forceinline__ float ex2f(float x) {
    float e; asm("ex2.approx.f32 %0, %1;" : "=f"(e) : "f"(x)); return e;
}

// ---------------- K0: P[4,G], c[G], and zero g_acc mean region ----------------
__global__ void k0_P(const float* __restrict__ Win, const float* __restrict__ bin,
                     const float* __restrict__ Kp) {
    int gtid = blockIdx.x * blockDim.x + threadIdx.x;
    if (gtid < B * G + B * D) g_acc[gtid] = 0.f;     // fused zero-init (validated R5/R6)

    int warp = gtid >> 5;
    int lane = threadIdx.x & 31;
    if (warp >= G) return;
    const float S = 1.4426950408889634f * 0.08838834764831843f;  // log2e / sqrt(128)
    float a0 = 0.f, a1 = 0.f, a2 = 0.f, a3 = 0.f, cb = 0.f;
    const float* krow = Kp + (size_t)warp * D;
#pragma unroll
    for (int i = 0; i < 4; i++) {
        int d = lane + 32 * i;
        float kv = krow[d];
        a0 = fmaf(kv, Win[0 * D + d], a0);
        a1 = fmaf(kv, Win[1 * D + d], a1);
        a2 = fmaf(kv, Win[2 * D + d], a2);
        a3 = fmaf(kv, Win[3 * D + d], a3);
        cb = fmaf(kv, bin[d], cb);
    }
#pragma unroll
    for (int off = 16; off; off >>= 1) {
        a0 += __shfl_down_sync(0xffffffffu, a0, off);
        a1 += __shfl_down_sync(0xffffffffu, a1, off);
        a2 += __shfl_down_sync(0xffffffffu, a2, off);
        a3 += __shfl_down_sync(0xffffffffu, a3, off);
        cb += __shfl_down_sync(0xffffffffu, cb, off);
    }
    if (lane == 0) {
        g_P4[warp] = make_float4(a0 * S, a1 * S, a2 * S, a3 * S);
        g_c[warp]  = cb * S;
    }
}

// ---------------- K12: persistent fused softmax row-norm + partial column-sum ----------------
// grid = 148 (1 block/SM, persistent). Each block loops over tasks
// task = (b, q-chunk); per task: pass A (R6-identical scores->exp->smem E,
// Z accumulate, clamped 1-deep prefetch), Z-reduce -> 1/Z, pass B writes the
// per-task partial w row to g_wpart with coalesced STG (NO atomics).
// Next task's m-vectors are prefetched right after pass A.
extern __shared__ float k12_smem[];
__global__ void __launch_bounds__(NT, 1) k12(const float* __restrict__ mut) {
    float* sE   = k12_smem;             // G * 8 floats, row k at sE + k*8
    float* zbuf = k12_smem + G * QB;    // 16 warps * 8
    float* sr   = zbuf + (NT / 32) * QB;// 8 floats

    const int tid  = threadIdx.x;
    const int lane = tid & 31, warp = tid >> 5;

    int task = blockIdx.x;
    if (task >= NTASK) return;

    // load m for first task
    float4 m[QB];
    {
        int b = task / NCHUNK;
        int q0 = (task - b * NCHUNK) * QB;
        const float4* mp = (const float4*)mut + (size_t)b * G + q0;
#pragma unroll
        for (int j = 0; j < QB; j++) m[j] = __ldg(mp + j);
    }

    while (task < NTASK) {
        const int next = task + NSM;

        float z[QB];
#pragma unroll
        for (int j = 0; j < QB; j++) z[j] = 0.f;

        // ---- Pass A: scores -> exp -> smem, accumulate Z (clamped prefetch) ----
        int k = tid;
        float4 p = __ldg(&g_P4[k]);
        float  c = __ldg(&g_c[k]);
        for (; k < G; k += NT) {
            int kn = (k + NT < G) ? (k + NT) : (G - 1);   // clamped: always in-bounds
            float4 pn = __ldg(&g_P4[kn]);
            float  cn = __ldg(&g_c[kn]);
            float e[QB];
#pragma unroll
            for (int j = 0; j < QB; j++) {
                float s = fmaf(m[j].x, p.x,
                          fmaf(m[j].y, p.y,
                          fmaf(m[j].z, p.z,
                          fmaf(m[j].w, p.w, c))));
                e[j] = ex2f(s);
                z[j] += e[j];
            }
            float4* row = (float4*)(sE + (size_t)k * QB);
            row[0] = make_float4(e[0], e[1], e[2], e[3]);
            row[1] = make_float4(e[4], e[5], e[6], e[7]);
            p = pn; c = cn;
        }

        // ---- prefetch next task's m (overlaps with Z-reduce + pass B) ----
        float4 mn[QB];
        {
            int tcl = (next < NTASK) ? next : task;       // clamped, always valid
            int bn = tcl / NCHUNK;
            int qn = (tcl - bn * NCHUNK) * QB;
            const float4* mp = (const float4*)mut + (size_t)bn * G + qn;
#pragma unroll
            for (int j = 0; j < QB; j++) mn[j] = __ldg(mp + j);
        }

        // ---- Z reduction: within warp (disjoint k per lane), then across warps ----
#pragma unroll
        for (int j = 0; j < QB; j++) {
#pragma unroll
            for (int off = 16; off; off >>= 1)
                z[j] += __shfl_down_sync(0xffffffffu, z[j], off);
        }
        if (lane == 0) {
#pragma unroll
            for (int j = 0; j < QB; j++) zbuf[warp * QB + j] = z[j];
        }
        __syncthreads();
        if (tid < QB) {
            float Z = 0.f;
#pragma unroll
            for (int w = 0; w < NT / 32; w++) Z += zbuf[w * QB + tid];
            sr[tid] = 1.0f / Z;
        }
        __syncthreads();

        float r[QB];
#pragma unroll
        for (int j = 0; j < QB; j++) r[j] = sr[j];

        // ---- Pass B: partial column sums -> coalesced STG (no atomics) ----
        float* wrow = g_wpart + (size_t)task * G;   // task = b*NCHUNK + chunk
        for (int kk = tid; kk < G; kk += NT) {
            const float4* row = (const float4*)(sE + (size_t)kk * QB);
            float4 a0 = row[0];
            float4 a1 = row[1];
            float wk = a0.x * r[0];
            wk = fmaf(a0.y, r[1], wk);
            wk = fmaf(a0.z, r[2], wk);
            wk = fmaf(a0.w, r[3], wk);
            wk = fmaf(a1.x, r[4], wk);
            wk = fmaf(a1.y, r[5], wk);
            wk = fmaf(a1.z, r[6], wk);
            wk = fmaf(a1.w, r[7], wk);
            wrow[kk] = wk;
        }

        __syncthreads();   // sE fully consumed before next task overwrites it
#pragma unroll
        for (int j = 0; j < QB; j++) m[j] = mn[j];
        task = next;
    }
}

// ---------------- K3a: reduce partials + V GEMV -> mean partials ----------------
// grid (137, 8), 256 threads. Block (kchunk of 32 k, batch b):
// phase 1 sums the 548 partial w rows for its 32 k (coalesced, warp-strided),
// phase 2 does the 32x128 V GEMV and atomically adds into the mean region.
__global__ void __launch_bounds__(256) k3a(const float* __restrict__ V) {
    __shared__ float wsum[8][32];
    __shared__ float wfin[32];
    const int b  = blockIdx.y;
    const int k0 = blockIdx.x * 32;
    const int kk  = threadIdx.x & 31;
    const int wrp = threadIdx.x >> 5;

    float acc = 0.f;
    const float* base = g_wpart + (size_t)b * NCHUNK * G + k0 + kk;
    for (int ch = wrp; ch < NCHUNK; ch += 8)
        acc += __ldg(base + (size_t)ch * G);
    wsum[wrp][kk] = acc;
    __syncthreads();
    if (threadIdx.x < 32) {
        float w = 0.f;
#pragma unroll
        for (int i = 0; i < 8; i++) w += wsum[i][kk];
        wfin[kk] = w;
    }
    __syncthreads();
    if (threadIdx.x < D) {
        int d = threadIdx.x;
        float a = 0.f;
#pragma unroll
        for (int k = 0; k < 32; k++)
            a = fmaf(wfin[k], __ldg(&V[(size_t)(k0 + k) * D + d]), a);
        atomicAdd(&g_acc[B * G + b * D + d], a);
    }
}

// ---------------- K3b: GELU MLP head (validated R5/R6 version) ----------------
__global__ void k3b(const float* __restrict__ W1, const float* __restrict__ b1,
                    const float* __restrict__ W2, const float* __restrict__ b2,
                    float* __restrict__ out) {
    __shared__ float mean[D];
    __shared__ float h[H1];
    int b = blockIdx.x, tid = threadIdx.x;   // 256 threads
    if (tid < D) mean[tid] = g_acc[B * G + b * D + tid] * (1.0f / (float)G);
    __syncthreads();
    {   // h: 64 outputs x 4 threads each
        int hh = tid >> 2, part = tid & 3;
        float a = 0.f;
        for (int d = part; d < D; d += 4)
            a = fmaf(mean[d], __ldg(&W1[d * H1 + hh]), a);
        a += __shfl_down_sync(0xffffffffu, a, 2);
        a += __shfl_down_sync(0xffffffffu, a, 1);
        if (part == 0) {
            a += b1[hh];
            h[hh] = 0.5f * a * (1.0f + erff(a * 0.70710678118654752f));
        }
    }
    __syncthreads();
    if (tid < 128) {   // out: 26 outputs x 4 threads
        int o = tid >> 2, part = tid & 3;
        int oc = o < NOUT ? o : NOUT - 1;
        float s = 0.f;
        for (int j = part; j < H1; j += 4)
            s = fmaf(h[j], __ldg(&W2[j * NOUT + oc]), s);
        s += __shfl_down_sync(0xffffffffu, s, 2);
        s += __shfl_down_sync(0xffffffffu, s, 1);
        if (part == 0 && o < NOUT) out[b * NOUT + o] = s + b2[o];
    }
}

// ---------------- launch ----------------
extern "C" void kernel_launch(void* const* d_in, const int* in_sizes, int n_in,
                              void* d_out, int out_size) {
    const float* mut = (const float*)d_in[0];   // [8,4384,4]
    const float* V   = (const float*)d_in[1];   // [4384,128]
    const float* Win = (const float*)d_in[2];   // [4,128]
    const float* bin = (const float*)d_in[3];   // [128]
    const float* Kp  = (const float*)d_in[4];   // [4384,128]
    const float* W1  = (const float*)d_in[5];   // [128,64]
    const float* b1  = (const float*)d_in[6];   // [64]
    const float* W2  = (const float*)d_in[7];   // [64,26]
    const float* b2  = (const float*)d_in[8];   // [26]
    float* out = (float*)d_out;                 // [8,26]
    (void)in_sizes; (void)n_in; (void)out_size;

    k0_P<<<548, 256>>>(Win, bin, Kp);           // 548*8 warps = 4384 = G (+ mean zeroing)

    size_t smemK12 = (size_t)G * QB * 4 + (NT / 32) * QB * 4 + QB * 4;  // 140,832 B
    cudaFuncSetAttribute(k12, cudaFuncAttributeMaxDynamicSharedMemorySize, (int)smemK12);
    k12<<<NSM, NT, smemK12>>>(mut);             // persistent: 1 block/SM

    k3a<<<dim3(137, B), 256>>>(V);
    k3b<<<B, 256>>>(W1, b1, W2, b2, out);
}

// round 8
// speedup vs baseline: 1.0609x; 1.0609x over previous
#include <cuda_runtime.h>
#include <math.h>

#define G  4384
#define D  128
#define B  8
#define H1 64
#define NOUT 26
#define QB 8                  // queries per block in fused kernel (G/QB = 548 exact)
#define NT 512                // threads per block in fused kernel

// ---------------- device scratch ----------------
__device__ float4 g_P4[G];              // P'[k] = (W_in @ K^T)*scale*log2e
__device__ float  g_c[G];               // c'[k]
__device__ float  g_acc[B * G + B * D]; // [0,B*G): w column sums; then mean partials

__device__ __forceinline__ float ex2f(float x) {
    float e; asm("ex2.approx.f32 %0, %1;" : "=f"(e) : "f"(x)); return e;
}
__device__ __forceinline__ unsigned long long pk2(float lo, float hi) {
    unsigned long long d;
    asm("mov.b64 %0, {%1,%2};" : "=l"(d) : "f"(lo), "f"(hi));
    return d;
}
__device__ __forceinline__ unsigned long long fma2(unsigned long long a,
                                                   unsigned long long b,
                                                   unsigned long long c) {
    unsigned long long d;
    asm("fma.rn.f32x2 %0, %1, %2, %3;" : "=l"(d) : "l"(a), "l"(b), "l"(c));
    return d;
}
__device__ __forceinline__ void unpk2(unsigned long long v, float& lo, float& hi) {
    asm("mov.b64 {%0,%1}, %2;" : "=f"(lo), "=f"(hi) : "l"(v));
}

// ---------------- K0: P[4,G], c[G], and zero g_acc ----------------
__global__ void k0_P(const float* __restrict__ Win, const float* __restrict__ bin,
                     const float* __restrict__ Kp) {
    int gtid = blockIdx.x * blockDim.x + threadIdx.x;
    if (gtid < B * G + B * D) g_acc[gtid] = 0.f;     // fused zero-init

    int warp = gtid >> 5;
    int lane = threadIdx.x & 31;
    if (warp >= G) return;
    const float S = 1.4426950408889634f * 0.08838834764831843f;  // log2e / sqrt(128)
    float a0 = 0.f, a1 = 0.f, a2 = 0.f, a3 = 0.f, cb = 0.f;
    const float* krow = Kp + (size_t)warp * D;
#pragma unroll
    for (int i = 0; i < 4; i++) {
        int d = lane + 32 * i;
        float kv = krow[d];
        a0 = fmaf(kv, Win[0 * D + d], a0);
        a1 = fmaf(kv, Win[1 * D + d], a1);
        a2 = fmaf(kv, Win[2 * D + d], a2);
        a3 = fmaf(kv, Win[3 * D + d], a3);
        cb = fmaf(kv, bin[d], cb);
    }
#pragma unroll
    for (int off = 16; off; off >>= 1) {
        a0 += __shfl_down_sync(0xffffffffu, a0, off);
        a1 += __shfl_down_sync(0xffffffffu, a1, off);
        a2 += __shfl_down_sync(0xffffffffu, a2, off);
        a3 += __shfl_down_sync(0xffffffffu, a3, off);
        cb += __shfl_down_sync(0xffffffffu, cb, off);
    }
    if (lane == 0) {
        g_P4[warp] = make_float4(a0 * S, a1 * S, a2 * S, a3 * S);
        g_c[warp]  = cb * S;
    }
}

// ---------------- K12: fused softmax row-norm + column-sum (exp evaluated ONCE) ----------------
// Structure and numerics identical to the R6 kernel (139.8us validated).
// ONLY change: the pass-A score chain is computed with fma.rn.f32x2 packed
// over query pairs (IEEE-identical per lane), halving FMA-pipe issue count.
extern __shared__ float k12_smem[];
__global__ void __launch_bounds__(NT, 1) k12(const float* __restrict__ mut) {
    float* sE   = k12_smem;             // G * 8 floats, row k at sE + k*8
    float* zbuf = k12_smem + G * QB;    // 16 warps * 8
    float* sr   = zbuf + (NT / 32) * QB;// 8 floats

    const int tid  = threadIdx.x;
    const int b    = blockIdx.y;
    const int q0   = blockIdx.x * QB;
    const int lane = tid & 31, warp = tid >> 5;

    // 8 query m-vectors, packed into f32x2 pairs over (2i, 2i+1)
    unsigned long long pmx[4], pmy[4], pmz[4], pmw[4];
#pragma unroll
    for (int i = 0; i < 4; i++) {
        float4 m0 = __ldg((const float4*)mut + (size_t)b * G + q0 + 2 * i);
        float4 m1 = __ldg((const float4*)mut + (size_t)b * G + q0 + 2 * i + 1);
        pmx[i] = pk2(m0.x, m1.x);
        pmy[i] = pk2(m0.y, m1.y);
        pmz[i] = pk2(m0.z, m1.z);
        pmw[i] = pk2(m0.w, m1.w);
    }

    float z[QB];
#pragma unroll
    for (int j = 0; j < QB; j++) z[j] = 0.f;

    // ---- Pass A: scores -> exp -> smem, accumulate Z (clamped 1-deep prefetch) ----
    int k = tid;                        // tid < NT <= G, always valid
    float4 p = __ldg(&g_P4[k]);
    float  c = __ldg(&g_c[k]);
    for (; k < G; k += NT) {
        int kn = (k + NT < G) ? (k + NT) : (G - 1);   // clamped: always in-bounds
        float4 pn = __ldg(&g_P4[kn]);
        float  cn = __ldg(&g_c[kn]);

        unsigned long long px2 = pk2(p.x, p.x), py2 = pk2(p.y, p.y);
        unsigned long long pz2 = pk2(p.z, p.z), pw2 = pk2(p.w, p.w);
        unsigned long long cc2 = pk2(c, c);

        float e[QB];
#pragma unroll
        for (int i = 0; i < 4; i++) {
            unsigned long long s2 = fma2(pmw[i], pw2, cc2);
            s2 = fma2(pmz[i], pz2, s2);
            s2 = fma2(pmy[i], py2, s2);
            s2 = fma2(pmx[i], px2, s2);
            float s0, s1; unpk2(s2, s0, s1);
            float e0 = ex2f(s0), e1 = ex2f(s1);
            z[2 * i]     += e0;
            z[2 * i + 1] += e1;
            e[2 * i]     = e0;
            e[2 * i + 1] = e1;
        }
        float4* row = (float4*)(sE + (size_t)k * QB);
        row[0] = make_float4(e[0], e[1], e[2], e[3]);
        row[1] = make_float4(e[4], e[5], e[6], e[7]);
        p = pn; c = cn;
    }

    // ---- Z reduction: within warp (disjoint k per lane), then across warps ----
#pragma unroll
    for (int j = 0; j < QB; j++) {
#pragma unroll
        for (int off = 16; off; off >>= 1)
            z[j] += __shfl_down_sync(0xffffffffu, z[j], off);
    }
    if (lane == 0) {
#pragma unroll
        for (int j = 0; j < QB; j++) zbuf[warp * QB + j] = z[j];
    }
    __syncthreads();
    if (tid < QB) {
        float Z = 0.f;
#pragma unroll
        for (int w = 0; w < NT / 32; w++) Z += zbuf[w * QB + tid];
        sr[tid] = 1.0f / Z;
    }
    __syncthreads();

    float r[QB];
#pragma unroll
    for (int j = 0; j < QB; j++) r[j] = sr[j];

    // ---- Pass B: column partial sums (R6-proven: one scalar RED per k) ----
    for (int kk = tid; kk < G; kk += NT) {
        const float4* row = (const float4*)(sE + (size_t)kk * QB);
        float4 a0 = row[0];
        float4 a1 = row[1];
        float wk = a0.x * r[0];
        wk = fmaf(a0.y, r[1], wk);
        wk = fmaf(a0.z, r[2], wk);
        wk = fmaf(a0.w, r[3], wk);
        wk = fmaf(a1.x, r[4], wk);
        wk = fmaf(a1.y, r[5], wk);
        wk = fmaf(a1.z, r[6], wk);
        wk = fmaf(a1.w, r[7], wk);
        atomicAdd(&g_acc[b * G + kk], wk);
    }
}

// ---------------- K3a: mean partials = w @ V (all batches per block) ----------------
__global__ void k3a(const float* __restrict__ V) {
    int chunk = blockIdx.x;          // 0..136, 32 k each
    int d = threadIdx.x;             // 128
    int k0 = chunk * 32;
    float acc[B];
#pragma unroll
    for (int b = 0; b < B; b++) acc[b] = 0.f;
    for (int k = k0; k < k0 + 32; k++) {
        float v = __ldg(&V[(size_t)k * D + d]);
#pragma unroll
        for (int b = 0; b < B; b++) acc[b] = fmaf(g_acc[b * G + k], v, acc[b]);
    }
#pragma unroll
    for (int b = 0; b < B; b++) atomicAdd(&g_acc[B * G + b * D + d], acc[b]);
}

// ---------------- K3b: GELU MLP head (validated) ----------------
__global__ void k3b(const float* __restrict__ W1, const float* __restrict__ b1,
                    const float* __restrict__ W2, const float* __restrict__ b2,
                    float* __restrict__ out) {
    __shared__ float mean[D];
    __shared__ float h[H1];
    int b = blockIdx.x, tid = threadIdx.x;   // 256 threads
    if (tid < D) mean[tid] = g_acc[B * G + b * D + tid] * (1.0f / (float)G);
    __syncthreads();
    {   // h: 64 outputs x 4 threads each
        int hh = tid >> 2, part = tid & 3;
        float a = 0.f;
        for (int d = part; d < D; d += 4)
            a = fmaf(mean[d], __ldg(&W1[d * H1 + hh]), a);
        a += __shfl_down_sync(0xffffffffu, a, 2);
        a += __shfl_down_sync(0xffffffffu, a, 1);
        if (part == 0) {
            a += b1[hh];
            h[hh] = 0.5f * a * (1.0f + erff(a * 0.70710678118654752f));
        }
    }
    __syncthreads();
    if (tid < 128) {   // out: 26 outputs x 4 threads
        int o = tid >> 2, part = tid & 3;
        int oc = o < NOUT ? o : NOUT - 1;
        float s = 0.f;
        for (int j = part; j < H1; j += 4)
            s = fmaf(h[j], __ldg(&W2[j * NOUT + oc]), s);
        s += __shfl_down_sync(0xffffffffu, s, 2);
        s += __shfl_down_sync(0xffffffffu, s, 1);
        if (part == 0 && o < NOUT) out[b * NOUT + o] = s + b2[o];
    }
}

// ---------------- launch ----------------
extern "C" void kernel_launch(void* const* d_in, const int* in_sizes, int n_in,
                              void* d_out, int out_size) {
    const float* mut = (const float*)d_in[0];   // [8,4384,4]
    const float* V   = (const float*)d_in[1];   // [4384,128]
    const float* Win = (const float*)d_in[2];   // [4,128]
    const float* bin = (const float*)d_in[3];   // [128]
    const float* Kp  = (const float*)d_in[4];   // [4384,128]
    const float* W1  = (const float*)d_in[5];   // [128,64]
    const float* b1  = (const float*)d_in[6];   // [64]
    const float* W2  = (const float*)d_in[7];   // [64,26]
    const float* b2  = (const float*)d_in[8];   // [26]
    float* out = (float*)d_out;                 // [8,26]
    (void)in_sizes; (void)n_in; (void)out_size;

    k0_P<<<548, 256>>>(Win, bin, Kp);           // 548*8 warps = 4384 = G (+ g_acc zeroing)

    size_t smemK12 = (size_t)G * QB * 4 + (NT / 32) * QB * 4 + QB * 4;  // 140,832 B
    cudaFuncSetAttribute(k12, cudaFuncAttributeMaxDynamicSharedMemorySize, (int)smemK12);
    k12<<<dim3(G / QB, B), NT, smemK12>>>(mut);

    k3a<<<137, D>>>(V);
    k3b<<<B, 256>>>(W1, b1, W2, b2, out);
}